// round 14
// baseline (speedup 1.0000x reference)
#include <cuda_runtime.h>
#include <cuda_fp16.h>
#include <cstdint>
#include <math.h>

#define FDIM 256
#define NB 8
#define NPATH 20
#define BDIM 8192
#define NROWS (NB * BDIM)          // 65536 GEMM rows (plane-major)
#define NCHUNK 8                   // K chunks of 32
#define GBN 64                     // n per CTA (per side; both sides computed)

// smem: per stage A 8KB + B 8KB; 3 stages
#define A_STAGE_B 8192
#define STAGE_B 16384
#define SMEM_TOTAL (3 * STAGE_B)   // 49152

// ---------------- scratch (device globals) ----------------
// A fp16 fragment-packed: [plane 8][btile 64][chunk 8][kstep 2][m16 8][lane 32][4 regs]
__device__ uint4 g_xth[(size_t)8 * 64 * 8 * 512];          // 32MB
// B fp16 fragment-packed: [g 4][nt 4][chunk 8][s 2][n8l 8][kstep 2][lane 32][uint2]
__device__ uint2 g_wth[(size_t)4 * 4 * 8 * 1024];          // 1MB
__device__ __half g_Lh[(size_t)NROWS * FDIM];              // 32MB  [row][n] ROW-major
__device__ __half g_Rh[(size_t)NROWS * FDIM];              // 32MB  [row][n] ROW-major
__device__ float g_Wc[FDIM * 64];
__device__ float g_sig[FDIM * 4];

__constant__ int c_masks[8] = {0, 1, 2, 4, 3, 5, 6, 7};
__constant__ int c_plut[64] = {
     0, -1, -1, -1,   -1,  1, -1, -1,   -1, -1,  2, -1,   -1, -1, -1,  3,
    -1,  4, -1, -1,    5, -1,  6, -1,   -1,  7, -1,  8,   -1, -1,  9, -1,
    -1, -1, 10, -1,   -1, 11, -1, 12,   13, -1, 14, -1,   -1, 15, -1, -1,
    -1, -1, -1, 16,   -1, -1, 17, -1,   -1, 18, -1, -1,   19, -1, -1, -1
};
__constant__ int c_grade_of_plane[8] = {0, 1, 1, 1, 2, 2, 2, 3};

// ---------------- helpers ----------------
__device__ __forceinline__ uint32_t pack_h2(float lo, float hi) {
    uint32_t r;   // low 16 bits = lo (smaller k index)
    asm("cvt.rn.f16x2.f32 %0, %1, %2;" : "=r"(r) : "f"(hi), "f"(lo));
    return r;
}
__device__ __forceinline__ uint32_t smem_u32(const void* p) {
    uint32_t r;
    asm("{ .reg .u64 t; cvta.to.shared.u64 t, %1; cvt.u32.u64 %0, t; }" : "=r"(r) : "l"(p));
    return r;
}
__device__ __forceinline__ void cp16(uint32_t sdst, const void* gsrc) {
    asm volatile("cp.async.cg.shared.global [%0], [%1], 16;" :: "r"(sdst), "l"(gsrc));
}
__device__ __forceinline__ void cp_commit() { asm volatile("cp.async.commit_group;"); }
template <int N> __device__ __forceinline__ void cp_wait() {
    asm volatile("cp.async.wait_group %0;" :: "n"(N));
}
__device__ __forceinline__ void mma_f16(float* c, const uint32_t* a, const uint32_t* b) {
    asm volatile(
        "mma.sync.aligned.m16n8k16.row.col.f32.f16.f16.f32 "
        "{%0,%1,%2,%3}, {%4,%5,%6,%7}, {%8,%9}, {%0,%1,%2,%3};"
        : "+f"(c[0]), "+f"(c[1]), "+f"(c[2]), "+f"(c[3])
        : "r"(a[0]), "r"(a[1]), "r"(a[2]), "r"(a[3]), "r"(b[0]), "r"(b[1]));
}

// ---------------------------------------------------------------------------
// B pack (+ folded prep): unchanged from R13
// ---------------------------------------------------------------------------
__global__ void __launch_bounds__(256) sgp_wprep(const float* __restrict__ wL,
                                                 const float* __restrict__ wR,
                                                 const float* __restrict__ w_gp,
                                                 const float* __restrict__ a_norm) {
    int pid = blockIdx.x * 256 + threadIdx.x;   // 0 .. 131071
    {
        int lane  = pid & 31;
        int kstep = (pid >> 5) & 1;
        int n8l   = (pid >> 6) & 7;
        int s     = (pid >> 9) & 1;
        int c     = (pid >> 10) & 7;
        int nt    = (pid >> 13) & 3;
        int g     = (pid >> 15) & 3;
        int gq = lane >> 2, t4 = lane & 3;
        int n = nt * 64 + n8l * 8 + gq;
        int k0 = c * 32 + kstep * 16 + 2 * t4;
        const float* w = s ? wR : wL;
        uint32_t b0 = pack_h2(w[((size_t)n * 256 + k0) * 4 + g],
                              w[((size_t)n * 256 + k0 + 1) * 4 + g]);
        uint32_t b1 = pack_h2(w[((size_t)n * 256 + k0 + 8) * 4 + g],
                              w[((size_t)n * 256 + k0 + 9) * 4 + g]);
        g_wth[pid] = make_uint2(b0, b1);
    }
    if (pid < FDIM * 64) {
        int n = pid >> 6;
        int t = pid & 63;
        int i = t >> 3, k = t & 7;
        int mi = c_masks[i], mk = c_masks[k];
        int gi = __popc(mi), gj = __popc(mi ^ mk), gk = __popc(mk);
        int p = c_plut[gi * 16 + gj * 4 + gk];
        int s = 0, aa = mi >> 1;
        while (aa) { s += __popc(aa & mk); aa >>= 1; }
        float sgn = (s & 1) ? -1.0f : 1.0f;
        g_Wc[n * 64 + t] = sgn * w_gp[n * NPATH + p];
        if (t < 4) g_sig[n * 4 + t] = 1.0f / (1.0f + expf(-a_norm[n * 4 + t]));
    }
}

// ---------------------------------------------------------------------------
// A pack/transpose -> fp16 fragments (unchanged from R13)
// ---------------------------------------------------------------------------
__global__ void __launch_bounds__(256) sgp_xt(const float* __restrict__ x) {
    int btile = blockIdx.x >> 3, chunk = blockIdx.x & 7;
    int t = threadIdx.x;
    int lane = t & 31, m16 = t >> 5;
    int gq = lane >> 2, t4 = lane & 3;
    int row0 = btile * 128 + m16 * 16 + gq;
#pragma unroll
    for (int ks = 0; ks < 2; ks++) {
        int k0 = chunk * 32 + ks * 16 + 2 * t4;
        float v[2][4][8];
#pragma unroll
        for (int r = 0; r < 2; r++) {
            int b = row0 + r * 8;
            const int cols[4] = {k0, k0 + 1, k0 + 8, k0 + 9};
#pragma unroll
            for (int ci = 0; ci < 4; ci++) {
                const float4* q = (const float4*)(x + ((size_t)b * 256 + cols[ci]) * 8);
                *(float4*)&v[r][ci][0] = q[0];
                *(float4*)&v[r][ci][4] = q[1];
            }
        }
#pragma unroll
        for (int p = 0; p < 8; p++) {
            uint32_t r0 = pack_h2(v[0][0][p], v[0][1][p]);
            uint32_t r1 = pack_h2(v[1][0][p], v[1][1][p]);
            uint32_t r2 = pack_h2(v[0][2][p], v[0][3][p]);
            uint32_t r3 = pack_h2(v[1][2][p], v[1][3][p]);
            size_t idx = ((((size_t)(p * 64 + btile) * 8 + chunk) * 2 + ks) * 8 + m16) * 32 + lane;
            g_xth[idx] = make_uint4(r0, r1, r2, r3);
        }
    }
}

// ---------------------------------------------------------------------------
// fp16 mma.sync GEMM (m16n8k16) — mainloop unchanged; D now stored ROW-major
// [row][n] as __half2 STG.32 (col is even: c0,c1 are adjacent n).
// ---------------------------------------------------------------------------
__global__ void __launch_bounds__(256, 2)
sgp_gemm() {
    extern __shared__ __align__(16) char sm[];

    const int tid = threadIdx.x;
    const int lane = tid & 31;
    const int wid = tid >> 5;
    const int gq = lane >> 2;
    const int t4 = lane & 3;
    const int wm = wid >> 2;
    const int wn = wid & 3;

    const int nt = blockIdx.x;
    const int n0 = nt * GBN;
    const int rt = blockIdx.y;
    const int plane = rt >> 6;
    const int btile = rt & 63;
    const int grade = c_grade_of_plane[plane];

    const uint4* Abase = g_xth + ((size_t)(plane * 64 + btile) * 8) * 512;
    const uint4* Bbase = (const uint4*)(g_wth + ((size_t)(grade * 4 + nt) * 8) * 1024);
    const uint32_t smb = smem_u32(sm);

    float acc[4][2][2][4];
#pragma unroll
    for (int mt = 0; mt < 4; mt++)
#pragma unroll
        for (int nn = 0; nn < 2; nn++)
#pragma unroll
            for (int s = 0; s < 2; s++)
#pragma unroll
                for (int r = 0; r < 4; r++) acc[mt][nn][s][r] = 0.0f;

    auto issue = [&](int c, int buf) {
        uint32_t sb = smb + buf * STAGE_B;
        const uint4* ga = Abase + (size_t)c * 512;
        const uint4* gb = Bbase + (size_t)c * 512;
#pragma unroll
        for (int q = 0; q < 2; q++) {
            int f = q * 256 + tid;
            cp16(sb + f * 16, ga + f);
            cp16(sb + A_STAGE_B + f * 16, gb + f);
        }
        cp_commit();
    };

    issue(0, 0);
    issue(1, 1);

    for (int c = 0; c < NCHUNK; c++) {
        const int buf = c % 3;
        if (c < NCHUNK - 1) cp_wait<1>(); else cp_wait<0>();
        __syncthreads();

        const uint32_t* As = (const uint32_t*)(sm + buf * STAGE_B);
        const uint32_t* Bs = (const uint32_t*)(sm + buf * STAGE_B + A_STAGE_B);

#pragma unroll
        for (int ks = 0; ks < 2; ks++) {
            uint32_t a[4][4];
#pragma unroll
            for (int mt = 0; mt < 4; mt++) {
                const uint4 v = *(const uint4*)(As + ((ks * 8 + wm * 4 + mt) * 32 + lane) * 4);
                a[mt][0] = v.x; a[mt][1] = v.y; a[mt][2] = v.z; a[mt][3] = v.w;
            }
            uint32_t b[2][2][2];
#pragma unroll
            for (int s = 0; s < 2; s++)
#pragma unroll
                for (int nn = 0; nn < 2; nn++) {
                    const uint2 v = *(const uint2*)(Bs +
                        (((s * 8 + wn * 2 + nn) * 2 + ks) * 32 + lane) * 2);
                    b[s][nn][0] = v.x; b[s][nn][1] = v.y;
                }
#pragma unroll
            for (int mt = 0; mt < 4; mt++)
#pragma unroll
                for (int nn = 0; nn < 2; nn++)
#pragma unroll
                    for (int s = 0; s < 2; s++)
                        mma_f16(acc[mt][nn][s], a[mt], b[s][nn]);
        }
        if (c + 2 < NCHUNK) issue(c + 2, (c + 2) % 3);
    }

    // store ROW-major [row][n]: c0,c1 -> half2 at (row, col); c2,c3 -> (row+8, col)
    const int rbase = plane * 8192 + btile * 128;
#pragma unroll
    for (int s = 0; s < 2; s++) {
        __half* Ob = s ? g_Rh : g_Lh;
#pragma unroll
        for (int mt = 0; mt < 4; mt++) {
#pragma unroll
            for (int nn = 0; nn < 2; nn++) {
                int row = rbase + wm * 64 + mt * 16 + gq;
                int col = n0 + wn * 16 + nn * 8 + 2 * t4;
                *(__half2*)(Ob + (size_t)row * FDIM + col) =
                    __floats2half2_rn(acc[mt][nn][s][0], acc[mt][nn][s][1]);
                *(__half2*)(Ob + (size_t)(row + 8) * FDIM + col) =
                    __floats2half2_rn(acc[mt][nn][s][2], acc[mt][nn][s][3]);
            }
        }
    }
}

// ---------------------------------------------------------------------------
// epilogue v5: block = 16 b x 32 n (512 thr); warp = fixed b, lanes over n.
// ALL global accesses lane-contiguous: x/out 32B/lane runs, L/R 2B/lane runs.
// Wc/sig/bias staged in smem with conflict-free pitches (65 / 5).
// ---------------------------------------------------------------------------
__global__ void __launch_bounds__(512) sgp_epi(const float* __restrict__ x,
                                               const float* __restrict__ bL,
                                               float* __restrict__ out) {
    __shared__ float sWc[32][65];
    __shared__ float sSig[32][5];
    __shared__ float sBias[32];

    const int tid = threadIdx.x;
    const int nblk = blockIdx.x & 7;
    const int bblk = blockIdx.x >> 3;
    const int n0 = nblk * 32;
    const int b0 = bblk * 16;

#pragma unroll
    for (int q = 0; q < 4; q++) {
        int f = q * 512 + tid;            // 0..2047
        sWc[f >> 6][f & 63] = g_Wc[(n0 + (f >> 6)) * 64 + (f & 63)];
    }
    if (tid < 128) sSig[tid >> 2][tid & 3] = g_sig[(n0 + (tid >> 2)) * 4 + (tid & 3)];
    if (tid < 32) sBias[tid] = bL[n0 + tid];
    __syncthreads();

    const int wid = tid >> 5;
    const int lane = tid & 31;
    const int n = n0 + lane;
    const int b = b0 + wid;

    float Lv[8], Rv[8];
#pragma unroll
    for (int i = 0; i < 8; i++) {
        size_t base = ((size_t)i * BDIM + b) * FDIM + n;
        Lv[i] = __half2float(g_Lh[base]);
        Rv[i] = __half2float(g_Rh[base]);
    }

    float xv[8];
    {
        const float4* xp = (const float4*)(x + ((size_t)b * FDIM + n) * NB);
        float4 x0 = xp[0], x1 = xp[1];
        xv[0] = x0.x; xv[1] = x0.y; xv[2] = x0.z; xv[3] = x0.w;
        xv[4] = x1.x; xv[5] = x1.y; xv[6] = x1.z; xv[7] = x1.w;
    }

    float xr[8];
    {
        float qs[4];
        qs[0] = Rv[0] * Rv[0];
        qs[1] = Rv[1] * Rv[1] + Rv[2] * Rv[2] + Rv[3] * Rv[3];
        qs[2] = Rv[4] * Rv[4] + Rv[5] * Rv[5] + Rv[6] * Rv[6];
        qs[3] = Rv[7] * Rv[7];
        float inv[4];
#pragma unroll
        for (int g = 0; g < 4; g++) {
            float nm = sqrtf(sqrtf(qs[g] * qs[g] + 1e-16f));
            inv[g] = 1.0f / (sSig[lane][g] * (nm - 1.0f) + 1.0f + 1e-6f);
        }
        xr[0] = Rv[0] * inv[0];
        xr[1] = Rv[1] * inv[1];  xr[2] = Rv[2] * inv[1];  xr[3] = Rv[3] * inv[1];
        xr[4] = Rv[4] * inv[2];  xr[5] = Rv[5] * inv[2];  xr[6] = Rv[6] * inv[2];
        xr[7] = Rv[7] * inv[3];
    }

    const int JT[64] = {
        0,1,2,3,4,5,6,7,
        1,0,4,5,2,3,7,6,
        2,4,0,6,1,7,3,5,
        3,5,6,0,7,1,2,4,
        4,2,1,7,0,6,5,3,
        5,3,7,1,6,0,4,2,
        6,7,3,2,5,4,0,1,
        7,6,5,4,3,2,1,0 };

    float gp[8] = {0, 0, 0, 0, 0, 0, 0, 0};
#pragma unroll
    for (int i = 0; i < 8; i++) {
#pragma unroll
        for (int k = 0; k < 8; k++)
            gp[JT[i * 8 + k]] += sWc[lane][i * 8 + k] * xv[i] * xr[k];
    }

    const float RS2 = 0.7071067811865476f;
    float o[8];
#pragma unroll
    for (int i = 0; i < 8; i++) o[i] = (Lv[i] + gp[i]) * RS2;
    o[0] += sBias[lane] * RS2;

    float4* op = (float4*)(out + ((size_t)b * FDIM + n) * NB);
    op[0] = make_float4(o[0], o[1], o[2], o[3]);
    op[1] = make_float4(o[4], o[5], o[6], o[7]);
}

// ---------------------------------------------------------------------------
// inputs: x, w_left, b_left, w_right, a_norm, w_gp
// ---------------------------------------------------------------------------
extern "C" void kernel_launch(void* const* d_in, const int* in_sizes, int n_in,
                              void* d_out, int out_size) {
    const float* x      = (const float*)d_in[0];
    const float* wL     = (const float*)d_in[1];
    const float* bLp    = (const float*)d_in[2];
    const float* wR     = (const float*)d_in[3];
    const float* a_norm = (const float*)d_in[4];
    const float* w_gp   = (const float*)d_in[5];
    float* out = (float*)d_out;

    sgp_wprep<<<512, 256>>>(wL, wR, w_gp, a_norm);   // B fp16 frags + Wc + sig
    sgp_xt<<<512, 256>>>(x);                         // A fp16 frags

    cudaFuncSetAttribute(sgp_gemm, cudaFuncAttributeMaxDynamicSharedMemorySize,
                         SMEM_TOTAL);
    dim3 gg(4, 512);
    sgp_gemm<<<gg, 256, SMEM_TOTAL>>>();

    // 512 b-blocks x 8 n-blocks = 4096 blocks of (16 b x 32 n)
    sgp_epi<<<4096, 512>>>(x, bLp, out);
}

// round 16
// speedup vs baseline: 1.3859x; 1.3859x over previous
#include <cuda_runtime.h>
#include <cuda_fp16.h>
#include <cstdint>
#include <math.h>

#define FDIM 256
#define NB 8
#define NPATH 20
#define BDIM 8192
#define NROWS (NB * BDIM)          // 65536 GEMM rows (plane-major)
#define NCHUNK 8                   // K chunks of 32
#define GBN 64                     // n per CTA (per side; both sides computed)

// smem: per stage A 8KB + B 8KB; 3 stages
#define A_STAGE_B 8192
#define STAGE_B 16384
#define SMEM_TOTAL (3 * STAGE_B)   // 49152

// ---------------- scratch (device globals) ----------------
// A fp16 fragment-packed: [plane 8][btile 64][chunk 8][kstep 2][m16 8][lane 32][4 regs]
__device__ uint4 g_xth[(size_t)8 * 64 * 8 * 512];          // 32MB
// B fp16 fragment-packed: [g 4][nt 4][chunk 8][s 2][n8l 8][kstep 2][lane 32][uint2]
__device__ uint2 g_wth[(size_t)4 * 4 * 8 * 1024];          // 1MB
__device__ __half g_Lh[(size_t)FDIM * NROWS];              // 32MB [n][row] col-major
__device__ __half g_Rh[(size_t)FDIM * NROWS];              // 32MB [n][row] col-major
__device__ unsigned short g_xpl[(size_t)8 * FDIM * BDIM];  // 16MB [plane][m][b] fp16 x
__device__ float g_Wc[FDIM * 64];
__device__ float g_sig[FDIM * 4];

__constant__ int c_masks[8] = {0, 1, 2, 4, 3, 5, 6, 7};
__constant__ int c_plut[64] = {
     0, -1, -1, -1,   -1,  1, -1, -1,   -1, -1,  2, -1,   -1, -1, -1,  3,
    -1,  4, -1, -1,    5, -1,  6, -1,   -1,  7, -1,  8,   -1, -1,  9, -1,
    -1, -1, 10, -1,   -1, 11, -1, 12,   13, -1, 14, -1,   -1, 15, -1, -1,
    -1, -1, -1, 16,   -1, -1, 17, -1,   -1, 18, -1, -1,   19, -1, -1, -1
};
__constant__ int c_grade_of_plane[8] = {0, 1, 1, 1, 2, 2, 2, 3};

// ---------------- helpers ----------------
__device__ __forceinline__ uint32_t pack_h2(float lo, float hi) {
    uint32_t r;   // low 16 bits = lo (smaller k index)
    asm("cvt.rn.f16x2.f32 %0, %1, %2;" : "=r"(r) : "f"(hi), "f"(lo));
    return r;
}
__device__ __forceinline__ uint32_t smem_u32(const void* p) {
    uint32_t r;
    asm("{ .reg .u64 t; cvta.to.shared.u64 t, %1; cvt.u32.u64 %0, t; }" : "=r"(r) : "l"(p));
    return r;
}
__device__ __forceinline__ void cp16(uint32_t sdst, const void* gsrc) {
    asm volatile("cp.async.cg.shared.global [%0], [%1], 16;" :: "r"(sdst), "l"(gsrc));
}
__device__ __forceinline__ void cp_commit() { asm volatile("cp.async.commit_group;"); }
template <int N> __device__ __forceinline__ void cp_wait() {
    asm volatile("cp.async.wait_group %0;" :: "n"(N));
}
__device__ __forceinline__ void mma_f16(float* c, const uint32_t* a, const uint32_t* b) {
    asm volatile(
        "mma.sync.aligned.m16n8k16.row.col.f32.f16.f16.f32 "
        "{%0,%1,%2,%3}, {%4,%5,%6,%7}, {%8,%9}, {%0,%1,%2,%3};"
        : "+f"(c[0]), "+f"(c[1]), "+f"(c[2]), "+f"(c[3])
        : "r"(a[0]), "r"(a[1]), "r"(a[2]), "r"(a[3]), "r"(b[0]), "r"(b[1]));
}

// ---------------------------------------------------------------------------
// B pack (+ folded prep): unchanged from R13
// ---------------------------------------------------------------------------
__global__ void __launch_bounds__(256) sgp_wprep(const float* __restrict__ wL,
                                                 const float* __restrict__ wR,
                                                 const float* __restrict__ w_gp,
                                                 const float* __restrict__ a_norm) {
    int pid = blockIdx.x * 256 + threadIdx.x;   // 0 .. 131071
    {
        int lane  = pid & 31;
        int kstep = (pid >> 5) & 1;
        int n8l   = (pid >> 6) & 7;
        int s     = (pid >> 9) & 1;
        int c     = (pid >> 10) & 7;
        int nt    = (pid >> 13) & 3;
        int g     = (pid >> 15) & 3;
        int gq = lane >> 2, t4 = lane & 3;
        int n = nt * 64 + n8l * 8 + gq;
        int k0 = c * 32 + kstep * 16 + 2 * t4;
        const float* w = s ? wR : wL;
        uint32_t b0 = pack_h2(w[((size_t)n * 256 + k0) * 4 + g],
                              w[((size_t)n * 256 + k0 + 1) * 4 + g]);
        uint32_t b1 = pack_h2(w[((size_t)n * 256 + k0 + 8) * 4 + g],
                              w[((size_t)n * 256 + k0 + 9) * 4 + g]);
        g_wth[pid] = make_uint2(b0, b1);
    }
    if (pid < FDIM * 64) {
        int n = pid >> 6;
        int t = pid & 63;
        int i = t >> 3, k = t & 7;
        int mi = c_masks[i], mk = c_masks[k];
        int gi = __popc(mi), gj = __popc(mi ^ mk), gk = __popc(mk);
        int p = c_plut[gi * 16 + gj * 4 + gk];
        int s = 0, aa = mi >> 1;
        while (aa) { s += __popc(aa & mk); aa >>= 1; }
        float sgn = (s & 1) ? -1.0f : 1.0f;
        g_Wc[n * 64 + t] = sgn * w_gp[n * NPATH + p];
        if (t < 4) g_sig[n * 4 + t] = 1.0f / (1.0f + expf(-a_norm[n * 4 + t]));
    }
}

// ---------------------------------------------------------------------------
// A pack/transpose -> fp16 fragments + plane-major fp16 x copy (g_xpl).
// Reuses the already-converted halves of the fragment packs for g_xpl.
// ---------------------------------------------------------------------------
__global__ void __launch_bounds__(256) sgp_xt(const float* __restrict__ x) {
    int btile = blockIdx.x >> 3, chunk = blockIdx.x & 7;
    int t = threadIdx.x;
    int lane = t & 31, m16 = t >> 5;
    int gq = lane >> 2, t4 = lane & 3;
    int row0 = btile * 128 + m16 * 16 + gq;
#pragma unroll
    for (int ks = 0; ks < 2; ks++) {
        int k0 = chunk * 32 + ks * 16 + 2 * t4;
        float v[2][4][8];
#pragma unroll
        for (int r = 0; r < 2; r++) {
            int b = row0 + r * 8;
            const int cols[4] = {k0, k0 + 1, k0 + 8, k0 + 9};
#pragma unroll
            for (int ci = 0; ci < 4; ci++) {
                const float4* q = (const float4*)(x + ((size_t)b * 256 + cols[ci]) * 8);
                *(float4*)&v[r][ci][0] = q[0];
                *(float4*)&v[r][ci][4] = q[1];
            }
        }
#pragma unroll
        for (int p = 0; p < 8; p++) {
            uint32_t r0 = pack_h2(v[0][0][p], v[0][1][p]);
            uint32_t r1 = pack_h2(v[1][0][p], v[1][1][p]);
            uint32_t r2 = pack_h2(v[0][2][p], v[0][3][p]);
            uint32_t r3 = pack_h2(v[1][2][p], v[1][3][p]);
            size_t idx = ((((size_t)(p * 64 + btile) * 8 + chunk) * 2 + ks) * 8 + m16) * 32 + lane;
            g_xth[idx] = make_uint4(r0, r1, r2, r3);
            // plane-major fp16 copy: g_xpl[p][m][b]
            size_t pb = (size_t)p * FDIM;
            g_xpl[(pb + k0    ) * BDIM + row0    ] = (unsigned short)(r0 & 0xffff);
            g_xpl[(pb + k0 + 1) * BDIM + row0    ] = (unsigned short)(r0 >> 16);
            g_xpl[(pb + k0    ) * BDIM + row0 + 8] = (unsigned short)(r1 & 0xffff);
            g_xpl[(pb + k0 + 1) * BDIM + row0 + 8] = (unsigned short)(r1 >> 16);
            g_xpl[(pb + k0 + 8) * BDIM + row0    ] = (unsigned short)(r2 & 0xffff);
            g_xpl[(pb + k0 + 9) * BDIM + row0    ] = (unsigned short)(r2 >> 16);
            g_xpl[(pb + k0 + 8) * BDIM + row0 + 8] = (unsigned short)(r3 & 0xffff);
            g_xpl[(pb + k0 + 9) * BDIM + row0 + 8] = (unsigned short)(r3 >> 16);
        }
    }
}

// ---------------------------------------------------------------------------
// fp16 mma.sync GEMM (m16n8k16) — unchanged from R13 (col-major fp16 D)
// ---------------------------------------------------------------------------
__global__ void __launch_bounds__(256, 2)
sgp_gemm() {
    extern __shared__ __align__(16) char sm[];

    const int tid = threadIdx.x;
    const int lane = tid & 31;
    const int wid = tid >> 5;
    const int gq = lane >> 2;
    const int t4 = lane & 3;
    const int wm = wid >> 2;
    const int wn = wid & 3;

    const int nt = blockIdx.x;
    const int n0 = nt * GBN;
    const int rt = blockIdx.y;
    const int plane = rt >> 6;
    const int btile = rt & 63;
    const int grade = c_grade_of_plane[plane];

    const uint4* Abase = g_xth + ((size_t)(plane * 64 + btile) * 8) * 512;
    const uint4* Bbase = (const uint4*)(g_wth + ((size_t)(grade * 4 + nt) * 8) * 1024);
    const uint32_t smb = smem_u32(sm);

    float acc[4][2][2][4];
#pragma unroll
    for (int mt = 0; mt < 4; mt++)
#pragma unroll
        for (int nn = 0; nn < 2; nn++)
#pragma unroll
            for (int s = 0; s < 2; s++)
#pragma unroll
                for (int r = 0; r < 4; r++) acc[mt][nn][s][r] = 0.0f;

    auto issue = [&](int c, int buf) {
        uint32_t sb = smb + buf * STAGE_B;
        const uint4* ga = Abase + (size_t)c * 512;
        const uint4* gb = Bbase + (size_t)c * 512;
#pragma unroll
        for (int q = 0; q < 2; q++) {
            int f = q * 256 + tid;
            cp16(sb + f * 16, ga + f);
            cp16(sb + A_STAGE_B + f * 16, gb + f);
        }
        cp_commit();
    };

    issue(0, 0);
    issue(1, 1);

    for (int c = 0; c < NCHUNK; c++) {
        const int buf = c % 3;
        if (c < NCHUNK - 1) cp_wait<1>(); else cp_wait<0>();
        __syncthreads();

        const uint32_t* As = (const uint32_t*)(sm + buf * STAGE_B);
        const uint32_t* Bs = (const uint32_t*)(sm + buf * STAGE_B + A_STAGE_B);

#pragma unroll
        for (int ks = 0; ks < 2; ks++) {
            uint32_t a[4][4];
#pragma unroll
            for (int mt = 0; mt < 4; mt++) {
                const uint4 v = *(const uint4*)(As + ((ks * 8 + wm * 4 + mt) * 32 + lane) * 4);
                a[mt][0] = v.x; a[mt][1] = v.y; a[mt][2] = v.z; a[mt][3] = v.w;
            }
            uint32_t b[2][2][2];
#pragma unroll
            for (int s = 0; s < 2; s++)
#pragma unroll
                for (int nn = 0; nn < 2; nn++) {
                    const uint2 v = *(const uint2*)(Bs +
                        (((s * 8 + wn * 2 + nn) * 2 + ks) * 32 + lane) * 2);
                    b[s][nn][0] = v.x; b[s][nn][1] = v.y;
                }
#pragma unroll
            for (int mt = 0; mt < 4; mt++)
#pragma unroll
                for (int nn = 0; nn < 2; nn++)
#pragma unroll
                    for (int s = 0; s < 2; s++)
                        mma_f16(acc[mt][nn][s], a[mt], b[s][nn]);
        }
        if (c + 2 < NCHUNK) issue(c + 2, (c + 2) % 3);
    }

    const int rbase = plane * 8192 + btile * 128;
#pragma unroll
    for (int s = 0; s < 2; s++) {
        __half* Ob = s ? g_Rh : g_Lh;
#pragma unroll
        for (int mt = 0; mt < 4; mt++) {
#pragma unroll
            for (int nn = 0; nn < 2; nn++) {
                int row = rbase + wm * 64 + mt * 16 + gq;
                int col = n0 + wn * 16 + nn * 8 + 2 * t4;
                Ob[(size_t)col * NROWS + row]           = __float2half_rn(acc[mt][nn][s][0]);
                Ob[(size_t)(col + 1) * NROWS + row]     = __float2half_rn(acc[mt][nn][s][1]);
                Ob[(size_t)col * NROWS + row + 8]       = __float2half_rn(acc[mt][nn][s][2]);
                Ob[(size_t)(col + 1) * NROWS + row + 8] = __float2half_rn(acc[mt][nn][s][3]);
            }
        }
    }
}

// ---------------------------------------------------------------------------
// epilogue v8: R10 shape (block 8n x 64b, warp fixed n, Wc broadcast), but
// thread's 2 points are (b0+lane, b0+lane+32) so L, R AND x loads are all
// lane-contiguous coalesced (x now fp16 from g_xpl). Only out stays scattered.
// ---------------------------------------------------------------------------
__global__ void __launch_bounds__(256) sgp_epi(const float* __restrict__ bL,
                                               float* __restrict__ out) {
    __shared__ float sWc[8][64];
    __shared__ float sSig[8][4];
    __shared__ float sBias[8];

    const int tid = threadIdx.x;
    const int nblk = blockIdx.x & 31;
    const int bblk = blockIdx.x >> 5;
    const int n0 = nblk * 8;
    const int b0 = bblk * 64;

#pragma unroll
    for (int q = 0; q < 2; q++) {
        int f = q * 256 + tid;            // 0..511
        sWc[f >> 6][f & 63] = g_Wc[(n0 + (f >> 6)) * 64 + (f & 63)];
    }
    if (tid < 32) sSig[tid >> 2][tid & 3] = g_sig[(n0 + (tid >> 2)) * 4 + (tid & 3)];
    if (tid < 8) sBias[tid] = bL[n0 + tid];
    __syncthreads();

    const int wid = tid >> 5;
    const int lane = tid & 31;
    const int n = n0 + wid;
    const int b = b0 + lane;              // pts: b and b+32

    float Lv[2][8], Rv[2][8], xv[2][8];
#pragma unroll
    for (int i = 0; i < 8; i++) {
        size_t rb = (size_t)n * NROWS + i * BDIM + b;
        Lv[0][i] = __half2float(g_Lh[rb]);
        Lv[1][i] = __half2float(g_Lh[rb + 32]);
        Rv[0][i] = __half2float(g_Rh[rb]);
        Rv[1][i] = __half2float(g_Rh[rb + 32]);
        size_t xb = ((size_t)i * FDIM + n) * BDIM + b;
        xv[0][i] = __half2float(__ushort_as_half(g_xpl[xb]));
        xv[1][i] = __half2float(__ushort_as_half(g_xpl[xb + 32]));
    }

    float xr[2][8];
#pragma unroll
    for (int p = 0; p < 2; p++) {
        float qs[4];
        qs[0] = Rv[p][0] * Rv[p][0];
        qs[1] = Rv[p][1] * Rv[p][1] + Rv[p][2] * Rv[p][2] + Rv[p][3] * Rv[p][3];
        qs[2] = Rv[p][4] * Rv[p][4] + Rv[p][5] * Rv[p][5] + Rv[p][6] * Rv[p][6];
        qs[3] = Rv[p][7] * Rv[p][7];
        float inv[4];
#pragma unroll
        for (int g = 0; g < 4; g++) {
            float nm = sqrtf(sqrtf(qs[g] * qs[g] + 1e-16f));
            inv[g] = 1.0f / (sSig[wid][g] * (nm - 1.0f) + 1.0f + 1e-6f);
        }
        xr[p][0] = Rv[p][0] * inv[0];
        xr[p][1] = Rv[p][1] * inv[1];  xr[p][2] = Rv[p][2] * inv[1];  xr[p][3] = Rv[p][3] * inv[1];
        xr[p][4] = Rv[p][4] * inv[2];  xr[p][5] = Rv[p][5] * inv[2];  xr[p][6] = Rv[p][6] * inv[2];
        xr[p][7] = Rv[p][7] * inv[3];
    }

    const int JT[64] = {
        0,1,2,3,4,5,6,7,
        1,0,4,5,2,3,7,6,
        2,4,0,6,1,7,3,5,
        3,5,6,0,7,1,2,4,
        4,2,1,7,0,6,5,3,
        5,3,7,1,6,0,4,2,
        6,7,3,2,5,4,0,1,
        7,6,5,4,3,2,1,0 };

    float gp[2][8] = {{0,0,0,0,0,0,0,0},{0,0,0,0,0,0,0,0}};
#pragma unroll
    for (int i = 0; i < 8; i++) {
#pragma unroll
        for (int k = 0; k < 8; k++) {
            float wcv = sWc[wid][i * 8 + k];      // uniform broadcast LDS
            int j = JT[i * 8 + k];
            gp[0][j] += wcv * xv[0][i] * xr[0][k];
            gp[1][j] += wcv * xv[1][i] * xr[1][k];
        }
    }

    const float RS2 = 0.7071067811865476f;
    const float bias = sBias[wid] * RS2;
#pragma unroll
    for (int p = 0; p < 2; p++) {
        float o[8];
#pragma unroll
        for (int i = 0; i < 8; i++) o[i] = (Lv[p][i] + gp[p][i]) * RS2;
        o[0] += bias;
        float4* op = (float4*)(out + ((size_t)(b + p * 32) * FDIM + n) * NB);
        op[0] = make_float4(o[0], o[1], o[2], o[3]);
        op[1] = make_float4(o[4], o[5], o[6], o[7]);
    }
}

// ---------------------------------------------------------------------------
// inputs: x, w_left, b_left, w_right, a_norm, w_gp
// ---------------------------------------------------------------------------
extern "C" void kernel_launch(void* const* d_in, const int* in_sizes, int n_in,
                              void* d_out, int out_size) {
    const float* x      = (const float*)d_in[0];
    const float* wL     = (const float*)d_in[1];
    const float* bLp    = (const float*)d_in[2];
    const float* wR     = (const float*)d_in[3];
    const float* a_norm = (const float*)d_in[4];
    const float* w_gp   = (const float*)d_in[5];
    float* out = (float*)d_out;

    sgp_wprep<<<512, 256>>>(wL, wR, w_gp, a_norm);   // B fp16 frags + Wc + sig
    sgp_xt<<<512, 256>>>(x);                         // A fp16 frags + x planes

    cudaFuncSetAttribute(sgp_gemm, cudaFuncAttributeMaxDynamicSharedMemorySize,
                         SMEM_TOTAL);
    dim3 gg(4, 512);
    sgp_gemm<<<gg, 256, SMEM_TOTAL>>>();

    // 32 n-blocks x 128 b-blocks = 4096 blocks of (8 n x 64 b)
    sgp_epi<<<4096, 256>>>(bLp, out);
}